// round 15
// baseline (speedup 1.0000x reference)
#include <cuda_runtime.h>
#include <cuda_fp16.h>
#include <cstdint>

#define LL      8192
#define BATCH   32
#define NF      128
#define NT      128
#define CPB     9             // CTAs per batch
#define NCTA    (CPB*BATCH)   // 288 <= 296 resident -> single wave, spin-safe
#define NU      64            // k128 slabs per batch
#define NTH     256

// ---- global tables / scratch ----
// C in mma-fragment order: [kk(512 k16-steps)][mtile(8)][lane(32)] -> uint4
// uint4 = {a0,a1,a2,a3}: a0=(r,c0,c0+1) a1=(r+8,..) a2=(r,c0+8,c0+9) a3=(r+8,..)
// where r = mtile*16 + lane/4, c0 = kk*16 + 2*(lane%4).
__device__ __align__(16) uint4  g_Cf[512*8*32];      // 2MB
__device__ __align__(16) __half g_Wh[NT*LL];         // [t][l] fp16
__device__ __align__(16) __half g_sigh[BATCH*LL];    // fp16 signal
__device__ __align__(16) float  g_part[NCTA*NF*NT];  // 18.9MB (L2-resident)
__device__ int g_cnt[BATCH];

// ---- smem: B only, 128t x 128k halfs, rows padded to 272B, double buffer ----
#define ROWB     272
#define TILEB    (128*ROWB)                // 34816
#define OFF_B(buf)  ((buf)*TILEB)
#define SMEM_DYN    (2*TILEB)              // 69632 -> 2 CTAs/SM

// ---- PTX helpers ----
__device__ __forceinline__ uint32_t smem_u32(const void* p) {
    uint32_t a;
    asm("{ .reg .u64 t; cvta.to.shared.u64 t, %1; cvt.u32.u64 %0, t; }" : "=r"(a) : "l"(p));
    return a;
}
__device__ __forceinline__ void ldsm4(uint32_t r[4], uint32_t addr) {
    asm volatile("ldmatrix.sync.aligned.m8n8.x4.shared.b16 {%0,%1,%2,%3}, [%4];"
                 : "=r"(r[0]), "=r"(r[1]), "=r"(r[2]), "=r"(r[3]) : "r"(addr));
}
__device__ __forceinline__ void mma16816v(float c[4], uint4 a,
                                          uint32_t b0, uint32_t b1) {
    asm volatile("mma.sync.aligned.m16n8k16.row.col.f32.f16.f16.f32 "
                 "{%0,%1,%2,%3}, {%4,%5,%6,%7}, {%8,%9}, {%0,%1,%2,%3};"
                 : "+f"(c[0]), "+f"(c[1]), "+f"(c[2]), "+f"(c[3])
                 : "r"(a.x), "r"(a.y), "r"(a.z), "r"(a.w), "r"(b0), "r"(b1));
}
__device__ __forceinline__ uint32_t hm2(uint32_t a, uint32_t b) {
    __half2 r = __hmul2(*(__half2*)&a, *(__half2*)&b);
    return *(uint32_t*)&r;
}
__device__ __forceinline__ float4 ldcg4(const float4* p) {
    float4 v;
    asm volatile("ld.global.cg.v4.f32 {%0,%1,%2,%3}, [%4];"
                 : "=f"(v.x), "=f"(v.y), "=f"(v.z), "=f"(v.w) : "l"(p));
    return v;
}

// exact fp32-phase cos replication (same numerics as all passing rounds)
__device__ __forceinline__ float cosv_ref(int f_, int l_) {
    int fi = (f_ * 4096) / 127;
    float fv = (float)fi, lf = (float)l_;
    const float TP = 6.2831854820251465f;
    const float DD = 1.7484556e-7f;
    float a  = TP * fv;
    float e1 = fmaf(TP, fv, -a);
    float bb = a * lf;
    float e2 = fmaf(a, lf, -bb);
    float eps = (DD * (fv * lf) - e1 * lf - e2) * (1.0f / 8192.0f);
    int m = (fi * l_) & (LL - 1);
    float x = (float)m * (1.0f / 4096.0f);
    float s, cc;
    sincospif(x, &s, &cc);
    return cc - eps * s;
}

// ---------------------------------------------------------------------------
// Single prep kernel: C fragments, W fp16 [t][l], sig fp16, counter zero.
// ---------------------------------------------------------------------------
__global__ void prep_tables(const float* __restrict__ sig) {
    int q = blockIdx.x * blockDim.x + threadIdx.x;
    if (q < BATCH) g_cnt[q] = 0;
    const int nC = 512 * 8 * 32;          // 131072 fragment uint4s
    const int nW = NT * LL / 4;           // 262144
    if (q < nC) {
        int kk = q >> 8;
        int mt = (q >> 5) & 7;
        int L  = q & 31;
        int f  = mt * 16 + (L >> 2);
        int c0 = kk * 16 + 2 * (L & 3);
        __half h[8];
        h[0] = __float2half_rn(cosv_ref(f,     c0));
        h[1] = __float2half_rn(cosv_ref(f,     c0 + 1));
        h[2] = __float2half_rn(cosv_ref(f + 8, c0));
        h[3] = __float2half_rn(cosv_ref(f + 8, c0 + 1));
        h[4] = __float2half_rn(cosv_ref(f,     c0 + 8));
        h[5] = __float2half_rn(cosv_ref(f,     c0 + 9));
        h[6] = __float2half_rn(cosv_ref(f + 8, c0 + 8));
        h[7] = __float2half_rn(cosv_ref(f + 8, c0 + 9));
        g_Cf[q] = *(uint4*)h;
    } else if (q < nC + nW) {
        int base = (q - nC) * 4;
        int t = base >> 13;
        int l = base & 8191;
        int tci = (t * 8191) / 127;
        float tcf = (float)tci;
        __half h[4];
#pragma unroll
        for (int i = 0; i < 4; i++) {
            float x = ((float)(l + i) - tcf) / 819.2f;
            h[i] = __float2half_rn(expf(-0.5f * (x * x)));
        }
        *(uint2*)&g_Wh[base] = *(uint2*)h;
    } else if (q < nC + nW + BATCH * LL / 4) {
        int base = (q - nC - nW) * 4;
        float4 v = *(const float4*)&sig[base];
        __half h[4];
        h[0] = __float2half_rn(v.x); h[1] = __float2half_rn(v.y);
        h[2] = __float2half_rn(v.z); h[3] = __float2half_rn(v.w);
        *(uint2*)&g_sigh[base] = *(uint2*)h;
    }
}

// ---------------------------------------------------------------------------
// GEMM: A via prefetched fragment LDGs (no smem), B via smem k128 double
// buffer (1 barrier/slab), cooperative split-k reduce (single wave).
// ---------------------------------------------------------------------------
__global__ void __launch_bounds__(NTH, 2)
gabor_mma(float* __restrict__ out) {
    extern __shared__ __align__(16) char smc[];
    const uint32_t smb = smem_u32(smc);
    const int tid = threadIdx.x, lane = tid & 31, wid = tid >> 5;
    const int c = blockIdx.x;
    const int b = c / CPB, j = c - b * CPB;
    const int u0 = j * NU / CPB;
    const int u1 = (j + 1) * NU / CPB;

    const int mt0 = (wid & 3) * 2;        // m-tile pair for this warp
    const int f0 = (wid & 3) * 32, t0 = (wid >> 2) * 64;

    auto Aload = [&](int kk, int mt) -> uint4 {
        return __ldg(g_Cf + ((size_t)kk * 8 + mt) * 32 + lane);
    };

    const int tp = tid >> 1, qq = tid & 1;
    auto buildP = [&](int u, int buf) {
        const uint4* wp = (const uint4*)(g_Wh + (size_t)tp * LL + u * 128 + qq * 64);
        const uint4* sp = (const uint4*)(g_sigh + (size_t)b * LL + u * 128 + qq * 64);
        char* ph = smc + OFF_B(buf) + tp * ROWB + qq * 128;
#pragma unroll
        for (int m = 0; m < 8; m++) {
            uint4 w = wp[m], s = sp[m], p;
            p.x = hm2(w.x, s.x); p.y = hm2(w.y, s.y);
            p.z = hm2(w.z, s.z); p.w = hm2(w.w, s.w);
            *(uint4*)(ph + 16 * m) = p;
        }
    };

    buildP(u0, 0);

    float acc[2][8][4];
#pragma unroll
    for (int m = 0; m < 2; m++)
#pragma unroll
        for (int n = 0; n < 8; n++)
#pragma unroll
            for (int q = 0; q < 4; q++) acc[m][n][q] = 0.0f;

    const uint32_t loff = (uint32_t)(lane & 15) * ROWB + (lane >> 4) * 16;
    const int r0 = lane >> 2, c0 = (lane & 3) * 2;

    const int kkend = u1 * 8;
    uint4 a0 = Aload(u0 * 8, mt0), a1 = Aload(u0 * 8, mt0 + 1);

    __syncthreads();

    for (int u = u0; u < u1; u++) {
        const int buf = (u - u0) & 1;
        const uint32_t bH = smb + OFF_B(buf) + t0 * ROWB + loff;
#pragma unroll
        for (int k16 = 0; k16 < 8; k16++) {
            const int kk = u * 8 + k16;
            uint4 an0, an1;
            const bool pf = (kk + 1 < kkend);
            if (pf) { an0 = Aload(kk + 1, mt0); an1 = Aload(kk + 1, mt0 + 1); }
            const uint32_t kb = (uint32_t)k16 * 32;
            uint32_t bh[4][4];
#pragma unroll
            for (int jj = 0; jj < 4; jj++)
                ldsm4(bh[jj], bH + jj * 16 * ROWB + kb);
#pragma unroll
            for (int jj = 0; jj < 4; jj++) {
                mma16816v(acc[0][2 * jj],     a0, bh[jj][0], bh[jj][2]);
                mma16816v(acc[0][2 * jj + 1], a0, bh[jj][1], bh[jj][3]);
                mma16816v(acc[1][2 * jj],     a1, bh[jj][0], bh[jj][2]);
                mma16816v(acc[1][2 * jj + 1], a1, bh[jj][1], bh[jj][3]);
            }
            if (pf) { a0 = an0; a1 = an1; }
        }
        if (u + 1 < u1) buildP(u + 1, buf ^ 1);
        __syncthreads();
    }

    // ---- store own segment ----
    float* dst = g_part + (size_t)c * (NF * NT);
#pragma unroll
    for (int m = 0; m < 2; m++)
#pragma unroll
        for (int n = 0; n < 8; n++) {
            const int f = f0 + 16 * m + r0;
            const int t = t0 + 16 * (n >> 1) + 8 * (n & 1) + c0;
            *(float2*)&dst[f * NT + t]       = make_float2(acc[m][n][0], acc[m][n][1]);
            *(float2*)&dst[(f + 8) * NT + t] = make_float2(acc[m][n][2], acc[m][n][3]);
        }

    // ---- cooperative arrival + spin (single wave => deadlock-free) ----
    __syncthreads();
    if (tid == 0) {
        __threadfence();
        atomicAdd(&g_cnt[b], 1);
        int v;
        do {
            asm volatile("ld.global.acquire.gpu.b32 %0, [%1];"
                         : "=r"(v) : "l"(&g_cnt[b]));
        } while (v < CPB);
    }
    __syncthreads();

    // ---- each of the 9 CTAs reduces its 1/9 slice (L2-hot, fixed order) ----
    {
        const int n4b = NF * NT / 4;
        const int s0 = j * n4b / CPB;
        const int s1 = (j + 1) * n4b / CPB;
        const float4* base = (const float4*)(g_part + (size_t)b * CPB * (NF * NT));
        float4* ob = (float4*)(out + (size_t)b * (NF * NT));
        for (int i = s0 + tid; i < s1; i += NTH) {
            float4 v0 = ldcg4(base + i);
            float4 v1 = ldcg4(base + 1 * n4b + i);
            float4 v2 = ldcg4(base + 2 * n4b + i);
            float4 v3 = ldcg4(base + 3 * n4b + i);
            float4 v4 = ldcg4(base + 4 * n4b + i);
            float4 v5 = ldcg4(base + 5 * n4b + i);
            float4 v6 = ldcg4(base + 6 * n4b + i);
            float4 v7 = ldcg4(base + 7 * n4b + i);
            float4 v8 = ldcg4(base + 8 * n4b + i);
            float4 a;
            a.x = ((((((((v0.x + v1.x) + v2.x) + v3.x) + v4.x) + v5.x) + v6.x) + v7.x) + v8.x);
            a.y = ((((((((v0.y + v1.y) + v2.y) + v3.y) + v4.y) + v5.y) + v6.y) + v7.y) + v8.y);
            a.z = ((((((((v0.z + v1.z) + v2.z) + v3.z) + v4.z) + v5.z) + v6.z) + v7.z) + v8.z);
            a.w = ((((((((v0.w + v1.w) + v2.w) + v3.w) + v4.w) + v5.w) + v6.w) + v7.w) + v8.w);
            ob[i] = a;
        }
    }
}

extern "C" void kernel_launch(void* const* d_in, const int* in_sizes, int n_in,
                              void* d_out, int out_size) {
    const float* sig = (const float*)d_in[0];
    float* out = (float*)d_out;

    int ptot = 512 * 8 * 32 + NT * LL / 4 + BATCH * LL / 4;
    prep_tables<<<(ptot + 255) / 256, 256>>>(sig);

    cudaFuncSetAttribute(gabor_mma, cudaFuncAttributeMaxDynamicSharedMemorySize, SMEM_DYN);
    gabor_mma<<<NCTA, NTH, SMEM_DYN>>>(out);
}